// round 10
// baseline (speedup 1.0000x reference)
#include <cuda_runtime.h>
#include <cuda_bf16.h>

#define H 512
#define W 512
#define OW 510
#define PLANE (H * W)
#define WIN_PER_WARP 30            // 32 lanes -> 30 window cols
#define COLGROUPS 17               // 17 * 30 = 510 exactly
#define NTASKS (OW * COLGROUPS)    // 510 * 17 = 8670 (one window row per task)
#define WARPS_PER_BLOCK 5
#define NBLOCKS (NTASKS / WARPS_PER_BLOCK)   // 1734 exactly

__device__ double       g_accum;   // zero-init; restored to 0 each call
__device__ unsigned int g_cnt;     // zero-init; restored to 0 each call

__global__ __launch_bounds__(WARPS_PER_BLOCK * 32, 8)
void ml_fused_kernel(const float* __restrict__ T, const float* __restrict__ V,
                     float* __restrict__ out)
{
    const int warp_id  = threadIdx.x >> 5;
    const int lane     = threadIdx.x & 31;
    const int warp_gid = blockIdx.x * WARPS_PER_BLOCK + warp_id;

    const int r  = warp_gid / COLGROUPS;          // window row 0..509
    const int cg = warp_gid % COLGROUPS;          // col group 0..16
    const int x  = cg * WIN_PER_WARP + lane;      // pixel column 0..511

    // ---- front-load ALL 18 loads (3 rows x 6 channels) -> MLP = 18 ----
    const int b0 = r * W + x;
    const int b1 = b0 + W;
    const int b2 = b1 + W;

    const float ta0 = T[0*PLANE + b0], ta1 = T[1*PLANE + b0], ta2 = T[2*PLANE + b0];
    const float va0 = V[0*PLANE + b0], va1 = V[1*PLANE + b0], va2 = V[2*PLANE + b0];
    const float tb0 = T[0*PLANE + b1], tb1 = T[1*PLANE + b1], tb2 = T[2*PLANE + b1];
    const float vb0 = V[0*PLANE + b1], vb1 = V[1*PLANE + b1], vb2 = V[2*PLANE + b1];
    const float tc0 = T[0*PLANE + b2], tc1 = T[1*PLANE + b2], tc2 = T[2*PLANE + b2];
    const float vc0 = V[0*PLANE + b2], vc1 = V[1*PLANE + b2], vc2 = V[2*PLANE + b2];

    // ---- column-segment stats over the 3 rows (22 values) ----
    float cs[22];
    cs[0]  = ta0 + tb0 + tc0;
    cs[1]  = ta1 + tb1 + tc1;
    cs[2]  = ta2 + tb2 + tc2;
    cs[3]  = va0 + vb0 + vc0;
    cs[4]  = va1 + vb1 + vc1;
    cs[5]  = va2 + vb2 + vc2;
    cs[6]  = ta0*ta0 + tb0*tb0 + tc0*tc0;
    cs[7]  = ta0*ta1 + tb0*tb1 + tc0*tc1;
    cs[8]  = ta0*ta2 + tb0*tb2 + tc0*tc2;
    cs[9]  = ta1*ta1 + tb1*tb1 + tc1*tc1;
    cs[10] = ta1*ta2 + tb1*tb2 + tc1*tc2;
    cs[11] = ta2*ta2 + tb2*tb2 + tc2*tc2;
    cs[12] = va0*va0 + va1*va1 + va2*va2
           + vb0*vb0 + vb1*vb1 + vb2*vb2
           + vc0*vc0 + vc1*vc1 + vc2*vc2;
    cs[13] = ta0*va0 + tb0*vb0 + tc0*vc0;
    cs[14] = ta0*va1 + tb0*vb1 + tc0*vc1;
    cs[15] = ta0*va2 + tb0*vb2 + tc0*vc2;
    cs[16] = ta1*va0 + tb1*vb0 + tc1*vc0;
    cs[17] = ta1*va1 + tb1*vb1 + tc1*vc1;
    cs[18] = ta1*va2 + tb1*vb2 + tc1*vc2;
    cs[19] = ta2*va0 + tb2*vb0 + tc2*vc0;
    cs[20] = ta2*va1 + tb2*vb1 + tc2*vc1;
    cs[21] = ta2*va2 + tb2*vb2 + tc2*vc2;

    // ---- horizontal window sum across cols lane..lane+2 ----
    #pragma unroll
    for (int k = 0; k < 22; k++) {
        const float a = __shfl_down_sync(0xffffffffu, cs[k], 1);
        const float b = __shfl_down_sync(0xffffffffu, cs[k], 2);
        cs[k] += a + b;
    }

    // ---- per-window value (Gram identity) ----
    const float inv9 = 1.0f / 9.0f;
    const float eps9 = 1e-7f * inv9;

    const float mu0 = cs[0] * inv9, mu1 = cs[1] * inv9, mu2 = cs[2] * inv9;
    const float sV0 = cs[3], sV1 = cs[4], sV2 = cs[5];

    const float a00 = cs[6]  * inv9 - mu0 * mu0 + eps9;
    const float a01 = cs[7]  * inv9 - mu0 * mu1;
    const float a02 = cs[8]  * inv9 - mu0 * mu2;
    const float a11 = cs[9]  * inv9 - mu1 * mu1 + eps9;
    const float a12 = cs[10] * inv9 - mu1 * mu2;
    const float a22 = cs[11] * inv9 - mu2 * mu2 + eps9;

    const float c00 = a11 * a22 - a12 * a12;
    const float c01 = a02 * a12 - a01 * a22;
    const float c02 = a01 * a12 - a02 * a11;
    const float c11 = a00 * a22 - a02 * a02;
    const float c12 = a01 * a02 - a00 * a12;
    const float c22 = a00 * a11 - a01 * a01;
    const float det = a00 * c00 + a01 * c01 + a02 * c02;
    const float rdet = 1.0f / det;

    const float u00 = cs[13] - mu0 * sV0;
    const float u01 = cs[14] - mu0 * sV1;
    const float u02 = cs[15] - mu0 * sV2;
    const float u10 = cs[16] - mu1 * sV0;
    const float u11 = cs[17] - mu1 * sV1;
    const float u12 = cs[18] - mu1 * sV2;
    const float u20 = cs[19] - mu2 * sV0;
    const float u21 = cs[20] - mu2 * sV1;
    const float u22 = cs[21] - mu2 * sV2;

    const float G00 = u00 * u00 + u01 * u01 + u02 * u02;
    const float G01 = u00 * u10 + u01 * u11 + u02 * u12;
    const float G02 = u00 * u20 + u01 * u21 + u02 * u22;
    const float G11 = u10 * u10 + u11 * u11 + u12 * u12;
    const float G12 = u10 * u20 + u11 * u21 + u12 * u22;
    const float G22 = u20 * u20 + u21 * u21 + u22 * u22;

    const float quadsum = (c00 * G00 + c11 * G11 + c22 * G22
                        + 2.f * (c01 * G01 + c02 * G02 + c12 * G12)) * rdet;

    const float pen = sV0 * sV0 + sV1 * sV1 + sV2 * sV2 + quadsum;
    float contrib = (lane < WIN_PER_WARP) ? (cs[12] - inv9 * pen) : 0.0f;

    // ---- warp reduction ----
    #pragma unroll
    for (int off = 16; off > 0; off >>= 1)
        contrib += __shfl_xor_sync(0xffffffffu, contrib, off);

    __shared__ float wsum[WARPS_PER_BLOCK];
    __shared__ bool  is_last;
    if (lane == 0) wsum[warp_id] = contrib;
    __syncthreads();

    if (threadIdx.x == 0) {
        float s = 0.f;
        #pragma unroll
        for (int i = 0; i < WARPS_PER_BLOCK; i++) s += wsum[i];
        atomicAdd(&g_accum, (double)s);
        __threadfence();
        unsigned int prev = atomicAdd(&g_cnt, 1u);
        is_last = (prev == NBLOCKS - 1);
    }
    __syncthreads();

    if (is_last && threadIdx.x == 0) {
        __threadfence();
        out[0] = (float)g_accum;
        g_accum = 0.0;
        g_cnt   = 0;
    }
}

extern "C" void kernel_launch(void* const* d_in, const int* in_sizes, int n_in,
                              void* d_out, int out_size)
{
    const float* target = (const float*)d_in[0];
    const float* style  = (const float*)d_in[1];
    float* out = (float*)d_out;

    ml_fused_kernel<<<NBLOCKS, WARPS_PER_BLOCK * 32>>>(target, style, out);
}

// round 11
// speedup vs baseline: 1.0418x; 1.0418x over previous
#include <cuda_runtime.h>
#include <cuda_bf16.h>

#define H 512
#define W 512
#define OW 510
#define PLANE (H * W)
#define RBLK 2                     // window rows per warp-task
#define WIN_PER_WARP 30            // 32 lanes -> 30 window cols
#define COLGROUPS 17               // 17 * 30 = 510 exactly
#define ROWGROUPS (OW / RBLK)      // 255 exactly
#define NTASKS (ROWGROUPS * COLGROUPS)   // 4335
#define WARPS_PER_BLOCK 5
#define NBLOCKS (NTASKS / WARPS_PER_BLOCK)   // 867 exactly

__device__ double       g_accum;   // zero-init; restored to 0 each call
__device__ unsigned int g_cnt;     // zero-init; restored to 0 each call

// per-pixel-row stats for one lane's column (22 values)
static __device__ __forceinline__ void row_stats(
    const float* __restrict__ T, const float* __restrict__ V,
    int base, float rs[22])
{
    const float t0 = T[0 * PLANE + base];
    const float t1 = T[1 * PLANE + base];
    const float t2 = T[2 * PLANE + base];
    const float v0 = V[0 * PLANE + base];
    const float v1 = V[1 * PLANE + base];
    const float v2 = V[2 * PLANE + base];
    rs[0]  = t0;      rs[1]  = t1;      rs[2]  = t2;
    rs[3]  = v0;      rs[4]  = v1;      rs[5]  = v2;
    rs[6]  = t0 * t0; rs[7]  = t0 * t1; rs[8]  = t0 * t2;
    rs[9]  = t1 * t1; rs[10] = t1 * t2; rs[11] = t2 * t2;
    rs[12] = v0 * v0 + v1 * v1 + v2 * v2;
    rs[13] = t0 * v0; rs[14] = t0 * v1; rs[15] = t0 * v2;
    rs[16] = t1 * v0; rs[17] = t1 * v1; rs[18] = t1 * v2;
    rs[19] = t2 * v0; rs[20] = t2 * v1; rs[21] = t2 * v2;
}

// horizontal 3-col window sum + per-window value via Gram identity; destroys cs
static __device__ __forceinline__ float window_value(float cs[22])
{
    #pragma unroll
    for (int k = 0; k < 22; k++) {
        const float a = __shfl_down_sync(0xffffffffu, cs[k], 1);
        const float b = __shfl_down_sync(0xffffffffu, cs[k], 2);
        cs[k] += a + b;
    }

    const float inv9 = 1.0f / 9.0f;
    const float eps9 = 1e-7f * inv9;

    const float mu0 = cs[0] * inv9, mu1 = cs[1] * inv9, mu2 = cs[2] * inv9;
    const float sV0 = cs[3], sV1 = cs[4], sV2 = cs[5];

    const float a00 = cs[6]  * inv9 - mu0 * mu0 + eps9;
    const float a01 = cs[7]  * inv9 - mu0 * mu1;
    const float a02 = cs[8]  * inv9 - mu0 * mu2;
    const float a11 = cs[9]  * inv9 - mu1 * mu1 + eps9;
    const float a12 = cs[10] * inv9 - mu1 * mu2;
    const float a22 = cs[11] * inv9 - mu2 * mu2 + eps9;

    // cofactors + det (no explicit inverse)
    const float c00 = a11 * a22 - a12 * a12;
    const float c01 = a02 * a12 - a01 * a22;
    const float c02 = a01 * a12 - a02 * a11;
    const float c11 = a00 * a22 - a02 * a02;
    const float c12 = a01 * a02 - a00 * a12;
    const float c22 = a00 * a11 - a01 * a01;
    const float det = a00 * c00 + a01 * c01 + a02 * c02;
    const float rdet = 1.0f / det;          // overlaps with Gram build below

    const float u00 = cs[13] - mu0 * sV0;
    const float u01 = cs[14] - mu0 * sV1;
    const float u02 = cs[15] - mu0 * sV2;
    const float u10 = cs[16] - mu1 * sV0;
    const float u11 = cs[17] - mu1 * sV1;
    const float u12 = cs[18] - mu1 * sV2;
    const float u20 = cs[19] - mu2 * sV0;
    const float u21 = cs[20] - mu2 * sV1;
    const float u22 = cs[21] - mu2 * sV2;

    // Gram: G_ij = sum_c u_ic * u_jc
    const float G00 = u00 * u00 + u01 * u01 + u02 * u02;
    const float G01 = u00 * u10 + u01 * u11 + u02 * u12;
    const float G02 = u00 * u20 + u01 * u21 + u02 * u22;
    const float G11 = u10 * u10 + u11 * u11 + u12 * u12;
    const float G12 = u10 * u20 + u11 * u21 + u12 * u22;
    const float G22 = u20 * u20 + u21 * u21 + u22 * u22;

    const float quadsum = (c00 * G00 + c11 * G11 + c22 * G22
                        + 2.f * (c01 * G01 + c02 * G02 + c12 * G12)) * rdet;

    const float pen = sV0 * sV0 + sV1 * sV1 + sV2 * sV2 + quadsum;
    return cs[12] - inv9 * pen;
}

__global__ __launch_bounds__(WARPS_PER_BLOCK * 32, 7)
void ml_fused_kernel(const float* __restrict__ T, const float* __restrict__ V,
                     float* __restrict__ out)
{
    const int warp_id  = threadIdx.x >> 5;
    const int lane     = threadIdx.x & 31;
    const int warp_gid = blockIdx.x * WARPS_PER_BLOCK + warp_id;

    const int rg = warp_gid / COLGROUPS;          // row group 0..254
    const int cg = warp_gid % COLGROUPS;          // col group 0..16
    const int r0 = rg * RBLK;                     // first window row of task
    const int x  = cg * WIN_PER_WARP + lane;      // pixel column 0..511

    const float lanemask = (lane < WIN_PER_WARP) ? 1.0f : 0.0f;
    float contrib = 0.0f;

    // shared middle rows r0+1, r0+2
    float P[22], tmp[22];
    row_stats(T, V, (r0 + 1) * W + x, P);
    row_stats(T, V, (r0 + 2) * W + x, tmp);
    #pragma unroll
    for (int k = 0; k < 22; k++) P[k] += tmp[k];

    // window row A: rows r0, r0+1, r0+2
    {
        float cs[22];
        row_stats(T, V, r0 * W + x, tmp);
        #pragma unroll
        for (int k = 0; k < 22; k++) cs[k] = P[k] + tmp[k];
        contrib += lanemask * window_value(cs);
    }
    // window row B: rows r0+1, r0+2, r0+3
    {
        float cs[22];
        row_stats(T, V, (r0 + 3) * W + x, tmp);
        #pragma unroll
        for (int k = 0; k < 22; k++) cs[k] = P[k] + tmp[k];
        contrib += lanemask * window_value(cs);
    }

    // warp reduction
    #pragma unroll
    for (int off = 16; off > 0; off >>= 1)
        contrib += __shfl_xor_sync(0xffffffffu, contrib, off);

    __shared__ float wsum[WARPS_PER_BLOCK];
    __shared__ bool  is_last;
    if (lane == 0) wsum[warp_id] = contrib;
    __syncthreads();

    if (threadIdx.x == 0) {
        float s = 0.f;
        #pragma unroll
        for (int i = 0; i < WARPS_PER_BLOCK; i++) s += wsum[i];
        atomicAdd(&g_accum, (double)s);
        __threadfence();
        unsigned int prev = atomicAdd(&g_cnt, 1u);
        is_last = (prev == NBLOCKS - 1);
    }
    __syncthreads();

    if (is_last && threadIdx.x == 0) {
        out[0] = (float)g_accum;      // all g_accum adds ordered before the
        g_accum = 0.0;                // counter reached NBLOCKS (fence above)
        g_cnt   = 0;
    }
}

extern "C" void kernel_launch(void* const* d_in, const int* in_sizes, int n_in,
                              void* d_out, int out_size)
{
    const float* target = (const float*)d_in[0];
    const float* style  = (const float*)d_in[1];
    float* out = (float*)d_out;

    ml_fused_kernel<<<NBLOCKS, WARPS_PER_BLOCK * 32>>>(target, style, out);
}